// round 2
// baseline (speedup 1.0000x reference)
#include <cuda_runtime.h>
#include <math.h>

#define C_DIM   1000
#define NVEC    250          // C_DIM / 4
#define B_MAX   65536

__device__ float g_row_loss[B_MAX];

__device__ __forceinline__ float bfly_max(float v) {
    #pragma unroll
    for (int o = 16; o > 0; o >>= 1) v = fmaxf(v, __shfl_xor_sync(0xffffffffu, v, o));
    return v;
}
__device__ __forceinline__ float bfly_sum(float v) {
    #pragma unroll
    for (int o = 16; o > 0; o >>= 1) v += __shfl_xor_sync(0xffffffffu, v, o);
    return v;
}

// One warp per row; 8 rows per CTA. Entire row lives in registers:
// lane l holds float4 vectors v = l + 32*i, i in [0,8). 32*8*4 = 1024 >= 1000.
// No __syncthreads, no shared memory in the hot kernel — warp shuffles only.
__global__ void __launch_bounds__(256, 2)
mvce_row(const float* __restrict__ outp, const float* __restrict__ tgtp, int B) {
    const int warp = threadIdx.x >> 5;
    const int lane = threadIdx.x & 31;
    const int row  = blockIdx.x * 8 + warp;
    if (row >= B) return;

    const float4* o4 = reinterpret_cast<const float4*>(outp + (size_t)row * C_DIM);
    const float4* t4 = reinterpret_cast<const float4*>(tgtp + (size_t)row * C_DIM);

    float4 o[8], t[8];
    // Front-batch all 16 LDG.128 per lane for maximum MLP.
    #pragma unroll
    for (int i = 0; i < 8; i++) {
        const int v = lane + 32 * i;
        if (v < NVEC) {
            o[i] = o4[v];
            t[i] = t4[v];
        } else {
            o[i] = make_float4(-3.0e38f, -3.0e38f, -3.0e38f, -3.0e38f);
            t[i] = make_float4(0.f, 0.f, 0.f, 0.f);
        }
    }

    // ---- Phase 1: row max (registers + butterfly) ----
    float mx = -3.0e38f;
    #pragma unroll
    for (int i = 0; i < 8; i++) {
        mx = fmaxf(mx, fmaxf(fmaxf(o[i].x, o[i].y), fmaxf(o[i].z, o[i].w)));
    }
    const float m = bfly_max(mx);

    // ---- Phase 2: negative-set sums (padding: t=0 -> neg, e=exp(-huge)=0) ----
    float sn = 0.f, tn = 0.f, an = 0.f, np = 0.f;
    #pragma unroll
    for (int i = 0; i < 8; i++) {
        {
            bool ng = t[i].x <= 0.5f; float e = __expf(o[i].x - m);
            sn += ng ? e : 0.f; tn += ng ? t[i].x : 0.f;
            an += ng ? t[i].x * o[i].x : 0.f; np += ng ? 0.f : 1.f;
        }
        {
            bool ng = t[i].y <= 0.5f; float e = __expf(o[i].y - m);
            sn += ng ? e : 0.f; tn += ng ? t[i].y : 0.f;
            an += ng ? t[i].y * o[i].y : 0.f; np += ng ? 0.f : 1.f;
        }
        {
            bool ng = t[i].z <= 0.5f; float e = __expf(o[i].z - m);
            sn += ng ? e : 0.f; tn += ng ? t[i].z : 0.f;
            an += ng ? t[i].z * o[i].z : 0.f; np += ng ? 0.f : 1.f;
        }
        {
            bool ng = t[i].w <= 0.5f; float e = __expf(o[i].w - m);
            sn += ng ? e : 0.f; tn += ng ? t[i].w : 0.f;
            an += ng ? t[i].w * o[i].w : 0.f; np += ng ? 0.f : 1.f;
        }
    }
    // Four independent butterfly chains — latencies overlap.
    sn = bfly_sum(sn);
    tn = bfly_sum(tn);
    an = bfly_sum(an);
    np = bfly_sum(np);

    // ---- Phase 3: per-positive loss (recompute exp only for positives) ----
    float L = 0.f;
    #pragma unroll
    for (int i = 0; i < 8; i++) {
        if (t[i].x > 0.5f)
            L += (tn + t[i].x) * (m + __logf(sn + __expf(o[i].x - m))) - an - t[i].x * o[i].x;
        if (t[i].y > 0.5f)
            L += (tn + t[i].y) * (m + __logf(sn + __expf(o[i].y - m))) - an - t[i].y * o[i].y;
        if (t[i].z > 0.5f)
            L += (tn + t[i].z) * (m + __logf(sn + __expf(o[i].z - m))) - an - t[i].z * o[i].z;
        if (t[i].w > 0.5f)
            L += (tn + t[i].w) * (m + __logf(sn + __expf(o[i].w - m))) - an - t[i].w * o[i].w;
    }
    L = bfly_sum(L);

    if (lane == 0) {
        g_row_loss[row] = (np > 0.f) ? (L / np)
                                     : (tn * (m + __logf(sn)) - an);
    }
}

__global__ void __launch_bounds__(1024)
mvce_final(float* __restrict__ out, int B) {
    __shared__ double sd[32];
    const int tid = threadIdx.x;
    double v = 0.0;
    for (int i = tid; i < B; i += 1024) v += (double)g_row_loss[i];
    #pragma unroll
    for (int o = 16; o > 0; o >>= 1) v += __shfl_xor_sync(0xffffffffu, v, o);
    if ((tid & 31) == 0) sd[tid >> 5] = v;
    __syncthreads();
    if (tid == 0) {
        double s = 0.0;
        #pragma unroll
        for (int i = 0; i < 32; i++) s += sd[i];
        out[0] = (float)(s / (double)B);
    }
}

extern "C" void kernel_launch(void* const* d_in, const int* in_sizes, int n_in,
                              void* d_out, int out_size) {
    const float* outp = (const float*)d_in[0];
    const float* tgtp = (const float*)d_in[1];
    const int B = in_sizes[0] / C_DIM;   // 65536

    mvce_row<<<(B + 7) / 8, 256>>>(outp, tgtp, B);
    mvce_final<<<1, 1024>>>((float*)d_out, B);
}

// round 3
// speedup vs baseline: 1.1730x; 1.1730x over previous
#include <cuda_runtime.h>
#include <math.h>

#define C_DIM    1000
#define NVEC     250        // C_DIM / 4
#define HALFVEC  125        // vectors per warp (2 warps per row)
#define ROWS_PER_CTA 4
#define NPART_MAX 16384

__device__ float g_part[NPART_MAX];

__device__ __forceinline__ float bfly_max(float v) {
    #pragma unroll
    for (int o = 16; o > 0; o >>= 1) v = fmaxf(v, __shfl_xor_sync(0xffffffffu, v, o));
    return v;
}
__device__ __forceinline__ float bfly_sum(float v) {
    #pragma unroll
    for (int o = 16; o > 0; o >>= 1) v += __shfl_xor_sync(0xffffffffu, v, o);
    return v;
}

// 256-thread CTA = 8 warps = 4 rows; each warp owns half a row (125 float4 pairs).
// Per lane: 4 float4 of output + 4 of target (32 data regs). Warp-pair combine
// through shared memory; CTA emits a single partial sum.
__global__ void __launch_bounds__(256, 3)
mvce_row(const float* __restrict__ outp, const float* __restrict__ tgtp, int B) {
    const int tid  = threadIdx.x;
    const int warp = tid >> 5;          // 0..7
    const int lane = tid & 31;
    const int pair = warp >> 1;         // row within CTA, 0..3
    const int half = warp & 1;          // which half of the row
    const int row  = blockIdx.x * ROWS_PER_CTA + pair;

    const float4* o4 = reinterpret_cast<const float4*>(outp + (size_t)row * C_DIM) + half * HALFVEC;
    const float4* t4 = reinterpret_cast<const float4*>(tgtp + (size_t)row * C_DIM) + half * HALFVEC;

    float4 o[4], t[4];
    #pragma unroll
    for (int i = 0; i < 4; i++) {
        const int v = lane + 32 * i;
        if (v < HALFVEC) {
            o[i] = o4[v];
            t[i] = t4[v];
        } else {
            o[i] = make_float4(-3.0e38f, -3.0e38f, -3.0e38f, -3.0e38f);
            t[i] = make_float4(0.f, 0.f, 0.f, 0.f);
        }
    }

    __shared__ float red[8][5];
    __shared__ float rl[ROWS_PER_CTA];

    // ---- Phase 1: row max ----
    float mx = -3.0e38f;
    #pragma unroll
    for (int i = 0; i < 4; i++)
        mx = fmaxf(mx, fmaxf(fmaxf(o[i].x, o[i].y), fmaxf(o[i].z, o[i].w)));
    mx = bfly_max(mx);
    if (lane == 0) red[warp][0] = mx;
    __syncthreads();
    const float m = fmaxf(red[pair * 2][0], red[pair * 2 + 1][0]);

    // ---- Phase 2: negative-set sums (padding: t=0 -> neg, exp(-huge)=0) ----
    float sn = 0.f, tn = 0.f, an = 0.f, np = 0.f;
    #pragma unroll
    for (int i = 0; i < 4; i++) {
        {
            bool ng = t[i].x <= 0.5f; float e = __expf(o[i].x - m);
            sn += ng ? e : 0.f; tn += ng ? t[i].x : 0.f;
            an += ng ? t[i].x * o[i].x : 0.f; np += ng ? 0.f : 1.f;
        }
        {
            bool ng = t[i].y <= 0.5f; float e = __expf(o[i].y - m);
            sn += ng ? e : 0.f; tn += ng ? t[i].y : 0.f;
            an += ng ? t[i].y * o[i].y : 0.f; np += ng ? 0.f : 1.f;
        }
        {
            bool ng = t[i].z <= 0.5f; float e = __expf(o[i].z - m);
            sn += ng ? e : 0.f; tn += ng ? t[i].z : 0.f;
            an += ng ? t[i].z * o[i].z : 0.f; np += ng ? 0.f : 1.f;
        }
        {
            bool ng = t[i].w <= 0.5f; float e = __expf(o[i].w - m);
            sn += ng ? e : 0.f; tn += ng ? t[i].w : 0.f;
            an += ng ? t[i].w * o[i].w : 0.f; np += ng ? 0.f : 1.f;
        }
    }
    sn = bfly_sum(sn);
    tn = bfly_sum(tn);
    an = bfly_sum(an);
    np = bfly_sum(np);
    if (lane == 0) { red[warp][1] = sn; red[warp][2] = tn; red[warp][3] = an; red[warp][4] = np; }
    __syncthreads();
    const float Sn = red[pair * 2][1] + red[pair * 2 + 1][1];
    const float Tn = red[pair * 2][2] + red[pair * 2 + 1][2];
    const float An = red[pair * 2][3] + red[pair * 2 + 1][3];
    const float Np = red[pair * 2][4] + red[pair * 2 + 1][4];

    // ---- Phase 3: per-positive loss ----
    float L = 0.f;
    #pragma unroll
    for (int i = 0; i < 4; i++) {
        if (t[i].x > 0.5f)
            L += (Tn + t[i].x) * (m + __logf(Sn + __expf(o[i].x - m))) - An - t[i].x * o[i].x;
        if (t[i].y > 0.5f)
            L += (Tn + t[i].y) * (m + __logf(Sn + __expf(o[i].y - m))) - An - t[i].y * o[i].y;
        if (t[i].z > 0.5f)
            L += (Tn + t[i].z) * (m + __logf(Sn + __expf(o[i].z - m))) - An - t[i].z * o[i].z;
        if (t[i].w > 0.5f)
            L += (Tn + t[i].w) * (m + __logf(Sn + __expf(o[i].w - m))) - An - t[i].w * o[i].w;
    }
    L = bfly_sum(L);
    __syncthreads();               // red[][0] reuse safe
    if (lane == 0) red[warp][0] = L;
    __syncthreads();
    if (half == 0 && lane == 0) {
        const float Ls = red[pair * 2][0] + red[pair * 2 + 1][0];
        rl[pair] = (Np > 0.f) ? (Ls / Np)
                              : (Tn * (m + __logf(Sn)) - An);
    }
    __syncthreads();
    if (tid == 0) {
        g_part[blockIdx.x] = rl[0] + rl[1] + rl[2] + rl[3];
    }
}

__global__ void __launch_bounds__(1024)
mvce_final(float* __restrict__ out, int nPart, int B) {
    __shared__ double sd[32];
    const int tid = threadIdx.x;
    double v = 0.0;
    for (int i = tid; i < nPart; i += 1024) v += (double)g_part[i];
    #pragma unroll
    for (int o = 16; o > 0; o >>= 1) v += __shfl_xor_sync(0xffffffffu, v, o);
    if ((tid & 31) == 0) sd[tid >> 5] = v;
    __syncthreads();
    if (tid == 0) {
        double s = 0.0;
        #pragma unroll
        for (int i = 0; i < 32; i++) s += sd[i];
        out[0] = (float)(s / (double)B);
    }
}

extern "C" void kernel_launch(void* const* d_in, const int* in_sizes, int n_in,
                              void* d_out, int out_size) {
    const float* outp = (const float*)d_in[0];
    const float* tgtp = (const float*)d_in[1];
    const int B = in_sizes[0] / C_DIM;      // 65536
    const int nCta = B / ROWS_PER_CTA;      // 16384

    mvce_row<<<nCta, 256>>>(outp, tgtp, B);
    mvce_final<<<1, 1024>>>((float*)d_out, nCta, B);
}

// round 4
// speedup vs baseline: 2.0614x; 1.7574x over previous
#include <cuda_runtime.h>
#include <math.h>

#define C_DIM    1000
#define HALFVEC  125        // float4 vectors per warp (2 warps per row)
#define ROWS_PER_CTA 4

__device__ double g_sum;

__device__ __forceinline__ float fast_ex2(float x) {
    float r;
    asm("ex2.approx.ftz.f32 %0, %1;" : "=f"(r) : "f"(x));
    return r;
}
__device__ __forceinline__ float fast_lg2(float x) {
    float r;
    asm("lg2.approx.ftz.f32 %0, %1;" : "=f"(r) : "f"(x));
    return r;
}

__device__ __forceinline__ float bfly_max(float v) {
    #pragma unroll
    for (int o = 16; o > 0; o >>= 1) v = fmaxf(v, __shfl_xor_sync(0xffffffffu, v, o));
    return v;
}
__device__ __forceinline__ float bfly_sum(float v) {
    #pragma unroll
    for (int o = 16; o > 0; o >>= 1) v += __shfl_xor_sync(0xffffffffu, v, o);
    return v;
}

#define L2E_F 1.4426950408889634f
#define LN2_F 0.6931471805599453f

__global__ void mvce_init() {
    if (threadIdx.x == 0) g_sum = 0.0;
}

// 256-thread CTA = 8 warps = 4 rows; each warp owns half a row.
// Per lane: 4 float4 of o, t, and e (exp kept, no recompute in phase 3).
// Per-element cost target ~15 issued ops, 2 MUFU.
__global__ void __launch_bounds__(256, 3)
mvce_row(const float* __restrict__ outp, const float* __restrict__ tgtp, int B) {
    const int tid  = threadIdx.x;
    const int warp = tid >> 5;          // 0..7
    const int lane = tid & 31;
    const int pair = warp >> 1;         // row within CTA
    const int half = warp & 1;
    const int row  = blockIdx.x * ROWS_PER_CTA + pair;

    const float4* o4 = reinterpret_cast<const float4*>(outp + (size_t)row * C_DIM) + half * HALFVEC;
    const float4* t4 = reinterpret_cast<const float4*>(tgtp + (size_t)row * C_DIM) + half * HALFVEC;

    float4 o[4], t[4];
    #pragma unroll
    for (int i = 0; i < 4; i++) {
        const int v = lane + 32 * i;
        if (v < HALFVEC) {
            o[i] = __ldcs(&o4[v]);
            t[i] = __ldcs(&t4[v]);
        } else {
            o[i] = make_float4(-3.0e38f, -3.0e38f, -3.0e38f, -3.0e38f);
            t[i] = make_float4(0.f, 0.f, 0.f, 0.f);
        }
    }

    __shared__ float red[8][8];
    __shared__ float rl[ROWS_PER_CTA];

    // ---- Phase 1: row max ----
    float mx = -3.0e38f;
    #pragma unroll
    for (int i = 0; i < 4; i++)
        mx = fmaxf(mx, fmaxf(fmaxf(o[i].x, o[i].y), fmaxf(o[i].z, o[i].w)));
    mx = bfly_max(mx);
    if (lane == 0) red[warp][0] = mx;
    __syncthreads();
    const float m  = fmaxf(red[pair * 2][0], red[pair * 2 + 1][0]);
    const float ml = -m * L2E_F;

    // ---- Phase 2: exps + sums. neg mask as float, all accumulation via FFMA.
    // Padding: o=-3e38 -> x=-inf -> e=0; t=0 -> counted negative; to=-0 harmless.
    float4 e[4];
    float sn = 0.f, tn = 0.f, an = 0.f, nn = 0.f, tt = 0.f;
    #pragma unroll
    for (int i = 0; i < 4; i++) {
        {
            float to = t[i].x * o[i].x;
            e[i].x = fast_ex2(fmaf(o[i].x, L2E_F, ml));
            float ngf = (t[i].x <= 0.5f) ? 1.f : 0.f;
            sn = fmaf(ngf, e[i].x, sn); tn = fmaf(ngf, t[i].x, tn);
            an = fmaf(ngf, to, an);     tt += to; nn += ngf;
        }
        {
            float to = t[i].y * o[i].y;
            e[i].y = fast_ex2(fmaf(o[i].y, L2E_F, ml));
            float ngf = (t[i].y <= 0.5f) ? 1.f : 0.f;
            sn = fmaf(ngf, e[i].y, sn); tn = fmaf(ngf, t[i].y, tn);
            an = fmaf(ngf, to, an);     tt += to; nn += ngf;
        }
        {
            float to = t[i].z * o[i].z;
            e[i].z = fast_ex2(fmaf(o[i].z, L2E_F, ml));
            float ngf = (t[i].z <= 0.5f) ? 1.f : 0.f;
            sn = fmaf(ngf, e[i].z, sn); tn = fmaf(ngf, t[i].z, tn);
            an = fmaf(ngf, to, an);     tt += to; nn += ngf;
        }
        {
            float to = t[i].w * o[i].w;
            e[i].w = fast_ex2(fmaf(o[i].w, L2E_F, ml));
            float ngf = (t[i].w <= 0.5f) ? 1.f : 0.f;
            sn = fmaf(ngf, e[i].w, sn); tn = fmaf(ngf, t[i].w, tn);
            an = fmaf(ngf, to, an);     tt += to; nn += ngf;
        }
    }
    sn = bfly_sum(sn); tn = bfly_sum(tn); an = bfly_sum(an);
    nn = bfly_sum(nn); tt = bfly_sum(tt);
    if (lane == 0) {
        red[warp][1] = sn; red[warp][2] = tn; red[warp][3] = an;
        red[warp][4] = nn; red[warp][5] = tt;
    }
    __syncthreads();
    const float Sn = red[pair * 2][1] + red[pair * 2 + 1][1];
    const float Tn = red[pair * 2][2] + red[pair * 2 + 1][2];
    const float An = red[pair * 2][3] + red[pair * 2 + 1][3];
    const float Nn = red[pair * 2][4] + red[pair * 2 + 1][4];
    const float Tt = red[pair * 2][5] + red[pair * 2 + 1][5];

    // ---- Phase 3: positives only, log2 domain. 5 issued ops/element. ----
    float sl = 0.f, stl = 0.f, tp = 0.f;
    #pragma unroll
    for (int i = 0; i < 4; i++) {
        if (t[i].x > 0.5f) { float l2 = fast_lg2(Sn + e[i].x); sl += l2; stl = fmaf(t[i].x, l2, stl); tp += t[i].x; }
        if (t[i].y > 0.5f) { float l2 = fast_lg2(Sn + e[i].y); sl += l2; stl = fmaf(t[i].y, l2, stl); tp += t[i].y; }
        if (t[i].z > 0.5f) { float l2 = fast_lg2(Sn + e[i].z); sl += l2; stl = fmaf(t[i].z, l2, stl); tp += t[i].z; }
        if (t[i].w > 0.5f) { float l2 = fast_lg2(Sn + e[i].w); sl += l2; stl = fmaf(t[i].w, l2, stl); tp += t[i].w; }
    }
    sl = bfly_sum(sl); stl = bfly_sum(stl); tp = bfly_sum(tp);
    __syncthreads();
    if (lane == 0) { red[warp][0] = sl; red[warp][6] = stl; red[warp][7] = tp; }
    __syncthreads();

    if (half == 0 && lane == 0) {
        const float Sl  = red[pair * 2][0] + red[pair * 2 + 1][0];
        const float Stl = red[pair * 2][6] + red[pair * 2 + 1][6];
        const float Tp  = red[pair * 2][7] + red[pair * 2 + 1][7];
        // 2 warps x 128 vecs x 4 = 1024 counted slots per row (padding is negative)
        const float Np  = 1024.f - Nn;
        const float StoP = Tt - An;   // sum over positives of t*o
        float L = Tn * Np * m + LN2_F * fmaf(Tn, Sl, Stl) + m * Tp - Np * An - StoP;
        rl[pair] = (Np > 0.f) ? (L / Np)
                              : (Tn * fmaf(LN2_F, fast_lg2(Sn), m) - An);
    }
    __syncthreads();
    if (tid == 0) {
        atomicAdd(&g_sum, (double)(rl[0] + rl[1] + rl[2] + rl[3]));
    }
}

__global__ void mvce_final(float* __restrict__ out, int B) {
    if (threadIdx.x == 0) out[0] = (float)(g_sum / (double)B);
}

extern "C" void kernel_launch(void* const* d_in, const int* in_sizes, int n_in,
                              void* d_out, int out_size) {
    const float* outp = (const float*)d_in[0];
    const float* tgtp = (const float*)d_in[1];
    const int B = in_sizes[0] / C_DIM;      // 65536
    const int nCta = B / ROWS_PER_CTA;      // 16384

    mvce_init<<<1, 32>>>();
    mvce_row<<<nCta, 256>>>(outp, tgtp, B);
    mvce_final<<<1, 32>>>((float*)d_out, B);
}